// round 15
// baseline (speedup 1.0000x reference)
#include <cuda_runtime.h>

#define IMG_H 200
#define IMG_W 200
#define VOLD 256
#define NPIX (IMG_H * IMG_W)

// Per-pixel ray parameters (SoA), filled by precompute kernel each call.
__device__ float4 g_par0[NPIX];   // {p0x, p0y, p0z, ddx}
__device__ float4 g_par1[NPIX];   // {ddy, ddz, scale, bitcast(smin | smax<<16)}

__global__ void __launch_bounds__(256) precompute_kernel(
    const float* __restrict__ k_inv,     // (1,3,3)
    const float* __restrict__ rt_inv,    // (1,4,4)
    const float* __restrict__ sdd_p,     // (1,)
    const float* __restrict__ affine_inv,// (4,4)
    const int*   __restrict__ n_samples_p)
{
    const int pix = blockIdx.x * blockDim.x + threadIdx.x;
    if (pix >= NPIX) return;
    const int u = pix % IMG_W;
    const int v = pix / IMG_W;

    const int   n   = *n_samples_p;
    const float sdd = *sdd_p;
    const float inv_nm1 = 1.0f / (float)(n - 1);
    const float px = (float)u, py = (float)v;

    const float tc0 = (k_inv[0] * px + k_inv[1] * py + k_inv[2]) * sdd;
    const float tc1 = (k_inv[3] * px + k_inv[4] * py + k_inv[5]) * sdd;
    const float tc2 = (k_inv[6] * px + k_inv[7] * py + k_inv[8]) * sdd;

    const float r00 = rt_inv[0],  r01 = rt_inv[1],  r02 = rt_inv[2],  t0 = rt_inv[3];
    const float r10 = rt_inv[4],  r11 = rt_inv[5],  r12 = rt_inv[6],  t1 = rt_inv[7];
    const float r20 = rt_inv[8],  r21 = rt_inv[9],  r22 = rt_inv[10], t2 = rt_inv[11];

    const float ray0 = r00 * tc0 + r01 * tc1 + r02 * tc2;
    const float ray1 = r10 * tc0 + r11 * tc1 + r12 * tc2;
    const float ray2 = r20 * tc0 + r21 * tc1 + r22 * tc2;

    const float a00 = affine_inv[0],  a01 = affine_inv[1],  a02 = affine_inv[2],  b0 = affine_inv[3];
    const float a10 = affine_inv[4],  a11 = affine_inv[5],  a12 = affine_inv[6],  b1 = affine_inv[7];
    const float a20 = affine_inv[8],  a21 = affine_inv[9],  a22 = affine_inv[10], b2 = affine_inv[11];

    const float p0x = a00 * t0 + a01 * t1 + a02 * t2 + b0;
    const float p0y = a10 * t0 + a11 * t1 + a12 * t2 + b1;
    const float p0z = a20 * t0 + a21 * t1 + a22 * t2 + b2;
    const float dx  = a00 * ray0 + a01 * ray1 + a02 * ray2;
    const float dy  = a10 * ray0 + a11 * ray1 + a12 * ray2;
    const float dz  = a20 * ray0 + a21 * ray1 + a22 * ray2;

    // Parametric AABB clip vs open interval (-1, VOLD); outside samples are 0.
    float tlo = 0.0f, thi = 1.0f;
    {
        const float P[3] = {p0x, p0y, p0z};
        const float D[3] = {dx, dy, dz};
        #pragma unroll
        for (int a = 0; a < 3; ++a) {
            if (fabsf(D[a]) > 1e-12f) {
                const float inv = 1.0f / D[a];
                const float ta = (-1.0f - P[a]) * inv;
                const float tb = ((float)VOLD - P[a]) * inv;
                tlo = fmaxf(tlo, fminf(ta, tb));
                thi = fminf(thi, fmaxf(ta, tb));
            } else if (P[a] <= -1.0f || P[a] >= (float)VOLD) {
                thi = -1.0f;  // empty
            }
        }
    }
    int smin = (int)floorf(tlo * (float)(n - 1)) - 1;
    int smax = (int)ceilf (thi * (float)(n - 1)) + 1;
    if (smin < 0)     smin = 0;
    if (smax > n - 1) smax = n - 1;
    if (smax < smin) { smin = 1; smax = 0; }   // empty, pack stays non-negative

    const float raylen = sqrtf(ray0 * ray0 + ray1 * ray1 + ray2 * ray2);
    const float scale  = raylen * inv_nm1;

    // Fold inv_nm1 into direction: pos(s) = p0 + s * dd
    g_par0[pix] = make_float4(p0x, p0y, p0z, dx * inv_nm1);
    g_par1[pix] = make_float4(dy * inv_nm1, dz * inv_nm1, scale,
                              __int_as_float(smin | (smax << 16)));
}

__device__ __forceinline__ float fetch_checked(const float* __restrict__ vol,
                                               int i, int j, int k) {
    if ((unsigned)i < (unsigned)VOLD && (unsigned)j < (unsigned)VOLD &&
        (unsigned)k < (unsigned)VOLD)
        return __ldg(vol + ((i * VOLD + j) * VOLD + k));
    return 0.0f;
}

// Pair (v[iz], v[iz+1]) via one aligned LDG.64 + predicated scalar fix-up.
__device__ __forceinline__ void load_zpair64(const float* __restrict__ row,
                                             int iz0, bool odd,
                                             float& a, float& b) {
    const float2 q = __ldg((const float2*)(row + iz0));
    float ext = 0.0f;
    if (odd) ext = __ldg(row + iz0 + 2);
    a = odd ? q.y : q.x;
    b = odd ? ext : q.y;
}

__device__ __forceinline__ float sample_one(const float* __restrict__ volume,
                                            float x, float y, float z) {
    const float flx = floorf(x), fly = floorf(y), flz = floorf(z);
    const int ix = (int)flx, iy = (int)fly, iz = (int)flz;
    const float wx = x - flx, wy = y - fly, wz = z - flz;

    float v000, v001, v010, v011, v100, v101, v110, v111;
    if ((unsigned)ix < (unsigned)(VOLD - 1) &&
        (unsigned)iy < (unsigned)(VOLD - 1) &&
        (unsigned)iz < (unsigned)(VOLD - 1)) {
        const int  iz0 = iz & ~1;
        const bool odd = (iz & 1) != 0;
        const float* row00 = volume + ((ix * VOLD + iy) * VOLD);
        load_zpair64(row00,                      iz0, odd, v000, v001);
        load_zpair64(row00 + VOLD,               iz0, odd, v010, v011);
        load_zpair64(row00 + VOLD * VOLD,        iz0, odd, v100, v101);
        load_zpair64(row00 + VOLD * VOLD + VOLD, iz0, odd, v110, v111);
    } else {
        v000 = fetch_checked(volume, ix,     iy,     iz);
        v001 = fetch_checked(volume, ix,     iy,     iz + 1);
        v010 = fetch_checked(volume, ix,     iy + 1, iz);
        v011 = fetch_checked(volume, ix,     iy + 1, iz + 1);
        v100 = fetch_checked(volume, ix + 1, iy,     iz);
        v101 = fetch_checked(volume, ix + 1, iy,     iz + 1);
        v110 = fetch_checked(volume, ix + 1, iy + 1, iz);
        v111 = fetch_checked(volume, ix + 1, iy + 1, iz + 1);
    }

    const float c00 = fmaf(wz, v001 - v000, v000);
    const float c01 = fmaf(wz, v011 - v010, v010);
    const float c10 = fmaf(wz, v101 - v100, v100);
    const float c11 = fmaf(wz, v111 - v110, v110);
    const float c0  = fmaf(wy, c01 - c00, c00);
    const float c1  = fmaf(wy, c11 - c10, c10);
    return fmaf(wx, c1 - c0, c0);
}

// One 128-thread block = one 2x2 pixel tile. Each of its 4 warps handles a
// contiguous QUARTER of the sample range (short dependency chains, 40000
// warps total); within a warp, 8 lanes per pixel cover 8 CONSECUTIVE samples
// per iteration (~17-voxel z-span) and the 4 rays share volume rows, keeping
// the reduced L1 footprint measured in R8/R11. Per-pixel partials combine
// via smem atomics.
#define BW (IMG_W / 2)      // 100 tiles across
#define BH (IMG_H / 2)      // 100 tiles down
#define NTILES (BW * BH)    // 10000 tiles -> blocks

__global__ void __launch_bounds__(128, 16) drr_kernel(
    const float* __restrict__ volume,
    float* __restrict__ out)
{
    __shared__ float s_acc[4];
    __shared__ float s_scale[4];
    __shared__ int   s_pix[4];

    const int tile = blockIdx.x;
    const int wid  = threadIdx.x >> 5;   // chunk id 0..3
    const int lane = threadIdx.x & 31;
    const int pixsel = lane >> 3;        // 0..3 -> pixel within 2x2 tile
    const int sl     = lane & 7;         // sample lane within pixel

    const int bu = tile % BW;
    const int bv = tile / BW;
    const int u = 2 * bu + (pixsel & 1);
    const int v = 2 * bv + (pixsel >> 1);
    const int pix = v * IMG_W + u;

    if (threadIdx.x < 4) s_acc[threadIdx.x] = 0.0f;

    const float4 P0 = __ldg(&g_par0[pix]);
    const float4 P1 = __ldg(&g_par1[pix]);
    const float p0x = P0.x, p0y = P0.y, p0z = P0.z, ddx = P0.w;
    const float ddy = P1.x, ddz = P1.y, scale = P1.z;
    const int   pack = __float_as_int(P1.w);
    const int   smin = pack & 0xFFFF;
    const int   smax = pack >> 16;

    if (wid == 0 && sl == 0) {          // one thread per pixel records meta
        s_scale[pixsel] = scale;
        s_pix[pixsel]   = pix;
    }
    __syncthreads();

    // This warp's contiguous sample chunk for its pixel.
    const int L        = smax - smin + 1;          // may be 0
    const int chunkLen = (L + 3) >> 2;
    const int start    = smin + wid * chunkLen;
    int       end      = start + chunkLen;
    if (end > smax + 1) end = smax + 1;

    float sum = 0.0f;
    #pragma unroll 2
    for (int s = start + sl; s < end; s += 8) {
        const float fs = (float)s;
        sum += sample_one(volume,
                          fmaf(fs, ddx, p0x),
                          fmaf(fs, ddy, p0y),
                          fmaf(fs, ddz, p0z));
    }

    // Reduce within the 8-lane group, then combine across warps via smem.
    #pragma unroll
    for (int o = 4; o > 0; o >>= 1)
        sum += __shfl_xor_sync(0xFFFFFFFFu, sum, o);

    if (sl == 0)
        atomicAdd(&s_acc[pixsel], sum);
    __syncthreads();

    if (threadIdx.x < 4)
        out[s_pix[threadIdx.x]] = s_acc[threadIdx.x] * s_scale[threadIdx.x];
}

extern "C" void kernel_launch(void* const* d_in, const int* in_sizes, int n_in,
                              void* d_out, int out_size) {
    const float* volume     = (const float*)d_in[0];
    const float* k_inv      = (const float*)d_in[1];
    const float* rt_inv     = (const float*)d_in[2];
    const float* sdd        = (const float*)d_in[3];
    const float* affine_inv = (const float*)d_in[4];
    const int*   n_samples  = (const int*)  d_in[5];
    float* out = (float*)d_out;

    precompute_kernel<<<(NPIX + 255) / 256, 256>>>(k_inv, rt_inv, sdd,
                                                   affine_inv, n_samples);

    drr_kernel<<<NTILES, 128>>>(volume, out);
}

// round 16
// speedup vs baseline: 1.1145x; 1.1145x over previous
#include <cuda_runtime.h>

#define IMG_H 200
#define IMG_W 200
#define VOLD 256
#define NPIX (IMG_H * IMG_W)

// Per-pixel ray parameters (SoA), filled by precompute kernel each call.
__device__ float4 g_par0[NPIX];   // {p0x, p0y, p0z, ddx}
__device__ float4 g_par1[NPIX];   // {ddy, ddz, scale, bitcast(smin | smax<<16)}

__global__ void __launch_bounds__(256) precompute_kernel(
    const float* __restrict__ k_inv,     // (1,3,3)
    const float* __restrict__ rt_inv,    // (1,4,4)
    const float* __restrict__ sdd_p,     // (1,)
    const float* __restrict__ affine_inv,// (4,4)
    const int*   __restrict__ n_samples_p)
{
    const int pix = blockIdx.x * blockDim.x + threadIdx.x;
    if (pix >= NPIX) return;
    const int u = pix % IMG_W;
    const int v = pix / IMG_W;

    const int   n   = *n_samples_p;
    const float sdd = *sdd_p;
    const float inv_nm1 = 1.0f / (float)(n - 1);
    const float px = (float)u, py = (float)v;

    const float tc0 = (k_inv[0] * px + k_inv[1] * py + k_inv[2]) * sdd;
    const float tc1 = (k_inv[3] * px + k_inv[4] * py + k_inv[5]) * sdd;
    const float tc2 = (k_inv[6] * px + k_inv[7] * py + k_inv[8]) * sdd;

    const float r00 = rt_inv[0],  r01 = rt_inv[1],  r02 = rt_inv[2],  t0 = rt_inv[3];
    const float r10 = rt_inv[4],  r11 = rt_inv[5],  r12 = rt_inv[6],  t1 = rt_inv[7];
    const float r20 = rt_inv[8],  r21 = rt_inv[9],  r22 = rt_inv[10], t2 = rt_inv[11];

    const float ray0 = r00 * tc0 + r01 * tc1 + r02 * tc2;
    const float ray1 = r10 * tc0 + r11 * tc1 + r12 * tc2;
    const float ray2 = r20 * tc0 + r21 * tc1 + r22 * tc2;

    const float a00 = affine_inv[0],  a01 = affine_inv[1],  a02 = affine_inv[2],  b0 = affine_inv[3];
    const float a10 = affine_inv[4],  a11 = affine_inv[5],  a12 = affine_inv[6],  b1 = affine_inv[7];
    const float a20 = affine_inv[8],  a21 = affine_inv[9],  a22 = affine_inv[10], b2 = affine_inv[11];

    const float p0x = a00 * t0 + a01 * t1 + a02 * t2 + b0;
    const float p0y = a10 * t0 + a11 * t1 + a12 * t2 + b1;
    const float p0z = a20 * t0 + a21 * t1 + a22 * t2 + b2;
    const float dx  = a00 * ray0 + a01 * ray1 + a02 * ray2;
    const float dy  = a10 * ray0 + a11 * ray1 + a12 * ray2;
    const float dz  = a20 * ray0 + a21 * ray1 + a22 * ray2;

    // Parametric AABB clip vs open interval (-1, VOLD); outside samples are 0.
    float tlo = 0.0f, thi = 1.0f;
    {
        const float P[3] = {p0x, p0y, p0z};
        const float D[3] = {dx, dy, dz};
        #pragma unroll
        for (int a = 0; a < 3; ++a) {
            if (fabsf(D[a]) > 1e-12f) {
                const float inv = 1.0f / D[a];
                const float ta = (-1.0f - P[a]) * inv;
                const float tb = ((float)VOLD - P[a]) * inv;
                tlo = fmaxf(tlo, fminf(ta, tb));
                thi = fminf(thi, fmaxf(ta, tb));
            } else if (P[a] <= -1.0f || P[a] >= (float)VOLD) {
                thi = -1.0f;  // empty
            }
        }
    }
    int smin = (int)floorf(tlo * (float)(n - 1)) - 1;
    int smax = (int)ceilf (thi * (float)(n - 1)) + 1;
    if (smin < 0)     smin = 0;
    if (smax > n - 1) smax = n - 1;
    if (smax < smin) { smin = 1; smax = 0; }   // empty, pack stays non-negative

    const float raylen = sqrtf(ray0 * ray0 + ray1 * ray1 + ray2 * ray2);
    const float scale  = raylen * inv_nm1;

    // Fold inv_nm1 into direction: pos(s) = p0 + s * dd
    g_par0[pix] = make_float4(p0x, p0y, p0z, dx * inv_nm1);
    g_par1[pix] = make_float4(dy * inv_nm1, dz * inv_nm1, scale,
                              __int_as_float(smin | (smax << 16)));
}

__device__ __forceinline__ float fetch_checked(const float* __restrict__ vol,
                                               int i, int j, int k) {
    if ((unsigned)i < (unsigned)VOLD && (unsigned)j < (unsigned)VOLD &&
        (unsigned)k < (unsigned)VOLD)
        return __ldg(vol + ((i * VOLD + j) * VOLD + k));
    return 0.0f;
}

// Pair (v[iz], v[iz+1]) via one aligned LDG.64 + predicated scalar fix-up.
__device__ __forceinline__ void load_zpair64(const float* __restrict__ row,
                                             int iz0, bool odd,
                                             float& a, float& b) {
    const float2 q = __ldg((const float2*)(row + iz0));
    float ext = 0.0f;
    if (odd) ext = __ldg(row + iz0 + 2);
    a = odd ? q.y : q.x;
    b = odd ? ext : q.y;
}

__device__ __forceinline__ float sample_one(const float* __restrict__ volume,
                                            float x, float y, float z) {
    const float flx = floorf(x), fly = floorf(y), flz = floorf(z);
    const int ix = (int)flx, iy = (int)fly, iz = (int)flz;
    const float wx = x - flx, wy = y - fly, wz = z - flz;

    float v000, v001, v010, v011, v100, v101, v110, v111;
    if ((unsigned)ix < (unsigned)(VOLD - 1) &&
        (unsigned)iy < (unsigned)(VOLD - 1) &&
        (unsigned)iz < (unsigned)(VOLD - 1)) {
        const int  iz0 = iz & ~1;
        const bool odd = (iz & 1) != 0;
        const float* row00 = volume + ((ix * VOLD + iy) * VOLD);
        load_zpair64(row00,                      iz0, odd, v000, v001);
        load_zpair64(row00 + VOLD,               iz0, odd, v010, v011);
        load_zpair64(row00 + VOLD * VOLD,        iz0, odd, v100, v101);
        load_zpair64(row00 + VOLD * VOLD + VOLD, iz0, odd, v110, v111);
    } else {
        v000 = fetch_checked(volume, ix,     iy,     iz);
        v001 = fetch_checked(volume, ix,     iy,     iz + 1);
        v010 = fetch_checked(volume, ix,     iy + 1, iz);
        v011 = fetch_checked(volume, ix,     iy + 1, iz + 1);
        v100 = fetch_checked(volume, ix + 1, iy,     iz);
        v101 = fetch_checked(volume, ix + 1, iy,     iz + 1);
        v110 = fetch_checked(volume, ix + 1, iy + 1, iz);
        v111 = fetch_checked(volume, ix + 1, iy + 1, iz + 1);
    }

    const float c00 = fmaf(wz, v001 - v000, v000);
    const float c01 = fmaf(wz, v011 - v010, v010);
    const float c10 = fmaf(wz, v101 - v100, v100);
    const float c11 = fmaf(wz, v111 - v110, v110);
    const float c0  = fmaf(wy, c01 - c00, c00);
    const float c1  = fmaf(wy, c11 - c10, c10);
    return fmaf(wx, c1 - c0, c0);
}

// One warp per pixel (R4 body, unchanged). Blocks are 512 threads = 16 warps
// mapped to a 4x4 image tile, so the 16 co-resident warps' rays sit within
// ~3 voxels in both u and v. Their gather bands overlap heavily, so lines
// fetched by one warp are L1 hits for its block-mates -> fewer L2 fills
// (fills were identified as the variable component of L1 busy work).
#define TW (IMG_W / 4)      // 50 tiles across
#define TH (IMG_H / 4)      // 50 tiles down
#define NTILES (TW * TH)    // 2500 blocks

__global__ void __launch_bounds__(512) drr_kernel(
    const float* __restrict__ volume,
    float* __restrict__ out)
{
    const int wid  = threadIdx.x >> 5;   // 0..15 -> pixel within 4x4 tile
    const int lane = threadIdx.x & 31;

    const int tile = blockIdx.x;
    const int tu = tile % TW;
    const int tv = tile / TW;
    const int u = 4 * tu + (wid & 3);
    const int v = 4 * tv + (wid >> 2);
    const int pix = v * IMG_W + u;

    const float4 P0 = __ldg(&g_par0[pix]);
    const float4 P1 = __ldg(&g_par1[pix]);
    const float p0x = P0.x, p0y = P0.y, p0z = P0.z, ddx = P0.w;
    const float ddy = P1.x, ddz = P1.y, scale = P1.z;
    const int   pack = __float_as_int(P1.w);
    const int   smin = pack & 0xFFFF;
    const int   smax = pack >> 16;

    float sum = 0.0f;
    #pragma unroll 2
    for (int s = smin + lane; s <= smax; s += 32) {
        const float fs = (float)s;
        sum += sample_one(volume,
                          fmaf(fs, ddx, p0x),
                          fmaf(fs, ddy, p0y),
                          fmaf(fs, ddz, p0z));
    }

    #pragma unroll
    for (int o = 16; o > 0; o >>= 1)
        sum += __shfl_xor_sync(0xFFFFFFFFu, sum, o);

    if (lane == 0)
        out[pix] = sum * scale;
}

extern "C" void kernel_launch(void* const* d_in, const int* in_sizes, int n_in,
                              void* d_out, int out_size) {
    const float* volume     = (const float*)d_in[0];
    const float* k_inv      = (const float*)d_in[1];
    const float* rt_inv     = (const float*)d_in[2];
    const float* sdd        = (const float*)d_in[3];
    const float* affine_inv = (const float*)d_in[4];
    const int*   n_samples  = (const int*)  d_in[5];
    float* out = (float*)d_out;

    precompute_kernel<<<(NPIX + 255) / 256, 256>>>(k_inv, rt_inv, sdd,
                                                   affine_inv, n_samples);

    drr_kernel<<<NTILES, 512>>>(volume, out);
}